// round 1
// baseline (speedup 1.0000x reference)
#include <cuda_runtime.h>
#include <math.h>

// QuantumIQPImageEmbedder — closed-form evaluation.
//
// Key identities (derivation in analysis):
//   rho4 = H4 (Psi Psi^H) H4, where Psi is the 16 x 2^16 reshape of the
//   phase-multiplied PRODUCT state (NO Hadamard transform needed: H16^2 = I).
//   G = Psi Psi^H factorizes per qubit because the Ising-phase difference
//   theta(i,m) - theta(j,m) only retains the a/b terms touching the 4 kept
//   qubits plus the two boundary couplings b3*dz3*z_m4 and b19*dz0*z_m19,
//   and the interior qubits contribute sum |s_q|^2 = 1 each.
// So the 2^20-amplitude simulation reduces to 16x16 closed-form algebra.

#define INV_SQRT2F 0.7071067811865476f

__device__ __forceinline__ float2 cmul(float2 a, float2 b) {
    return make_float2(a.x*b.x - a.y*b.y, a.x*b.y + a.y*b.x);
}
__device__ __forceinline__ float2 cmulc(float2 a, float2 b) { // a * conj(b)
    return make_float2(a.x*b.x + a.y*b.y, a.y*b.x - a.x*b.y);
}
__device__ __forceinline__ float2 cadd(float2 a, float2 b) {
    return make_float2(a.x + b.x, a.y + b.y);
}

__global__ void __launch_bounds__(256, 1)
iqp_embed_kernel(const float* __restrict__ x,        // (B,16,4,3)
                 const float* __restrict__ pos_w,    // (16,2)
                 const float* __restrict__ l1,       // (20,2)
                 const float* __restrict__ l2,       // (16,2)
                 const float* __restrict__ hw,       // (512,4)
                 const float* __restrict__ hb,       // (512,)
                 float* __restrict__ out)            // (B,512)
{
    const int b = blockIdx.x;
    const int t = threadIdx.x;          // 256 threads
    const int i = t >> 4, j = t & 15;   // G / rho4 element indices

    __shared__ float2 s[20][2];         // single-qubit states of current block
    __shared__ float  l1a[20], l1b[20];
    __shared__ float2 G[16][17];
    __shared__ float2 T[16][17];
    __shared__ float2 rho4s[3][16][16]; // quantum blocks 0, 1, 3
    __shared__ float2 rho012[64], rho123[64];
    __shared__ float2 rho01[16], rho23[16];
    __shared__ float2 rq0[4], rq3[4];
    __shared__ float2 rk0[64], rk3[64];
    __shared__ float  evals[4];
    __shared__ float  rbuf[8];
    __shared__ float  nrm;

    if (t < 20) { l1a[t] = l1[2*t]; l1b[t] = l1[2*t + 1]; }

    // ---------- Phase 1: rho4 for quantum blocks 0,1,3 ----------
    #pragma unroll
    for (int slot = 0; slot < 3; ++slot) {
        const int kb = (slot == 2) ? 3 : slot;

        if (t < 20) {
            const int q  = t;
            const int p  = 4*kb + q/5;
            const int jj = q % 5;
            float2 w0, w1;
            if (jj < 4) {
                const float* xp = x + ((size_t)(b*16 + p)*4 + jj)*3;
                float hx = 0.5f*xp[0], hy = 0.5f*xp[1], hz = 0.5f*xp[2];
                float cx = cosf(hx), sx = sinf(hx);
                float cy = cosf(hy), sy = sinf(hy);
                w0 = make_float2(cy*cx,  sy*sx);
                w1 = make_float2(sy*cx, -cy*sx);
                float cz = cosf(hz), sz = sinf(hz);
                float2 pz = make_float2(cz, -sz);   // e^{-i hz}
                w0 = cmul (w0, pz);                 // w0 * e^{-i hz}
                w1 = cmulc(w1, pz);                 // w1 * e^{+i hz}
            } else {
                float px = 0.5f*pos_w[2*p], py = 0.5f*pos_w[2*p + 1];
                float cx = cosf(px), sx = sinf(px);
                float cy = cosf(py), sy = sinf(py);
                w0 = make_float2(cy*cx,  sy*sx);
                w1 = make_float2(sy*cx, -cy*sx);
            }
            s[q][0] = make_float2((w0.x + w1.x)*INV_SQRT2F, (w0.y + w1.y)*INV_SQRT2F);
            s[q][1] = make_float2((w0.x - w1.x)*INV_SQRT2F, (w0.y - w1.y)*INV_SQRT2F);
        }
        __syncthreads();

        // --- G[i][j] (closed form) ---
        {
            const int i0 = (i>>3)&1, i1 = (i>>2)&1, i2 = (i>>1)&1, i3 = i&1;
            const int j0 = (j>>3)&1, j1 = (j>>2)&1, j2 = (j>>1)&1, j3 = j&1;

            float2 A = cmulc(s[0][i0], s[0][j0]);
            A = cmul(A, cmulc(s[1][i1], s[1][j1]));
            A = cmul(A, cmulc(s[2][i2], s[2][j2]));
            A = cmul(A, cmulc(s[3][i3], s[3][j3]));

            const float zi0 = 1.f - 2.f*i0, zi1 = 1.f - 2.f*i1;
            const float zi2 = 1.f - 2.f*i2, zi3 = 1.f - 2.f*i3;
            const float zj0 = 1.f - 2.f*j0, zj1 = 1.f - 2.f*j1;
            const float zj2 = 1.f - 2.f*j2, zj3 = 1.f - 2.f*j3;

            float D = l1a[0]*(zi0 - zj0) + l1a[1]*(zi1 - zj1)
                    + l1a[2]*(zi2 - zj2) + l1a[3]*(zi3 - zj3)
                    + l1b[0]*(zi0*zi1 - zj0*zj1)
                    + l1b[1]*(zi1*zi2 - zj1*zj2)
                    + l1b[2]*(zi2*zi3 - zj2*zj3);
            float2 ph = make_float2(cosf(0.5f*D), -sinf(0.5f*D));  // e^{-iD/2}

            const float p40 = s[4][0].x*s[4][0].x + s[4][0].y*s[4][0].y;
            const float p41 = s[4][1].x*s[4][1].x + s[4][1].y*s[4][1].y;
            const float pa0 = s[19][0].x*s[19][0].x + s[19][0].y*s[19][0].y;
            const float pa1 = s[19][1].x*s[19][1].x + s[19][1].y*s[19][1].y;

            const float d3 = zi3 - zj3, d0 = zi0 - zj0;
            const float phi4  = 0.5f*l1b[3] *d3;
            const float phi19 = 0.5f*l1b[19]*d0;
            float2 F4  = make_float2((p40 + p41)*cosf(phi4),  (p41 - p40)*sinf(phi4));
            float2 F19 = make_float2((pa0 + pa1)*cosf(phi19), (pa1 - pa0)*sinf(phi19));

            G[i][j] = cmul(cmul(A, ph), cmul(F4, F19));
        }
        __syncthreads();

        // --- T = H4 G (signs only, 1/4 scale) ---
        {
            float2 acc = make_float2(0.f, 0.f);
            #pragma unroll
            for (int kq = 0; kq < 16; ++kq) {
                float2 g = G[kq][j];
                if (__popc(i & kq) & 1) { acc.x -= g.x; acc.y -= g.y; }
                else                    { acc.x += g.x; acc.y += g.y; }
            }
            T[i][j] = make_float2(acc.x*0.25f, acc.y*0.25f);
        }
        __syncthreads();

        // --- rho4 = T H4 ---
        {
            float2 acc = make_float2(0.f, 0.f);
            #pragma unroll
            for (int kq = 0; kq < 16; ++kq) {
                float2 tt = T[i][kq];
                if (__popc(kq & j) & 1) { acc.x -= tt.x; acc.y -= tt.y; }
                else                    { acc.x += tt.x; acc.y += tt.y; }
            }
            rho4s[slot][i][j] = make_float2(acc.x*0.25f, acc.y*0.25f);
        }
        __syncthreads();
    }

    // ---------- Phase 2: partial traces ----------
    // rho4s[0] = block 0, rho4s[1] = block 1, rho4s[2] = block 3
    if (t < 64) {
        const int ii = t >> 3, jj = t & 7;
        rho012[t] = cadd(rho4s[0][2*ii    ][2*jj    ],
                         rho4s[0][2*ii + 1][2*jj + 1]);          // trace qubit 3
        rho123[t] = cadd(rho4s[0][ii][jj], rho4s[0][8 + ii][8 + jj]); // trace qubit 0
    } else if (t < 80) {
        const int u = t - 64, ii = u >> 2, jj = u & 3;
        float2 a = make_float2(0.f, 0.f), c = make_float2(0.f, 0.f);
        #pragma unroll
        for (int xx = 0; xx < 4; ++xx) {
            a = cadd(a, rho4s[0][4*ii + xx][4*jj + xx]);   // rho01 (block 0)
            c = cadd(c, rho4s[0][4*xx + ii][4*xx + jj]);   // rho23 (block 0)
        }
        rho01[u] = a; rho23[u] = c;
    } else if (t < 84) {
        const int u = t - 80, ii = u >> 1, jj = u & 1;
        float2 a = make_float2(0.f, 0.f), c = make_float2(0.f, 0.f);
        #pragma unroll
        for (int xx = 0; xx < 8; ++xx) {
            a = cadd(a, rho4s[1][8*ii + xx][8*jj + xx]);   // rho_q0 (block 1)
            c = cadd(c, rho4s[2][2*xx + ii][2*xx + jj]);   // rho_q3 (block 3)
        }
        rq0[u] = a; rq3[u] = c;
    }
    __syncthreads();

    if (t < 64) {
        const int ii = t >> 3, jj = t & 7;
        rk0[t] = cmul(rq3 [(ii>>2)*2 + (jj>>2)], rho01[(ii&3)*4 + (jj&3)]);
        rk3[t] = cmul(rho23[(ii>>1)*4 + (jj>>1)], rq0 [(ii&1)*2 + (jj&1)]);
    }
    __syncthreads();

    // ---------- Phase 3: Heisenberg expectation values ----------
    {
        const int kk = t >> 6;               // which e (0..3)
        const int idx = t & 63;
        const int oi = idx >> 3, oj = idx & 7;

        const float t1 = l2[2*kk];                      // a2[kk]
        const float t2 = l2[2*((kk - 1) & 15) + 1];     // b2[(kk-1)%16]
        const float t3 = l2[2*kk + 1];                  // b2[kk]
        const float c1 = cosf(t1), s1v = sinf(t1);
        const float c2 = cosf(t2), s2v = sinf(t2);
        const float c3 = cosf(t3), s3v = sinf(t3);

        // O = IZI * rot(t1, IXI) * rot(t2, XXI) * rot(t3, IXX); sparse expansion
        float2 val = make_float2(0.f, 0.f);
        #pragma unroll
        for (int pp = 0; pp < 2; ++pp) {
            const int p = pp ? (oi ^ 2) : oi;
            const float2 cA = pp ? make_float2(0.f, -s1v) : make_float2(c1, 0.f);
            #pragma unroll
            for (int qq = 0; qq < 2; ++qq) {
                const int q = qq ? (p ^ 6) : p;
                const float2 cB = qq ? make_float2(0.f, -s2v) : make_float2(c2, 0.f);
                float2 cC;
                if (q == oj)            cC = make_float2(c3, 0.f);
                else if (q == (oj ^ 3)) cC = make_float2(0.f, -s3v);
                else continue;
                val = cadd(val, cmul(cmul(cA, cB), cC));
            }
        }
        const float dsign = ((oi >> 1) & 1) ? -1.f : 1.f;
        val.x *= dsign; val.y *= dsign;

        const float2* rho = (kk == 0) ? rk0 : (kk == 1) ? rho012
                          : (kk == 2) ? rho123 : rk3;
        const float2 r = rho[oj*8 + oi];
        float contrib = val.x*r.x - val.y*r.y;   // Re(O[i,j] * rho[j,i])

        #pragma unroll
        for (int off = 16; off; off >>= 1)
            contrib += __shfl_down_sync(0xffffffffu, contrib, off);
        if ((t & 31) == 0) rbuf[t >> 5] = contrib;
    }
    __syncthreads();
    if (t < 4) evals[t] = rbuf[2*t] + rbuf[2*t + 1];
    __syncthreads();

    // ---------- Phase 4: head + L2 normalize ----------
    const float e0 = evals[0], e1 = evals[1], e2 = evals[2], e3 = evals[3];
    const int o0 = t, o1 = t + 256;
    float v0 = hb[o0] + e0*hw[o0*4] + e1*hw[o0*4+1] + e2*hw[o0*4+2] + e3*hw[o0*4+3];
    float v1 = hb[o1] + e0*hw[o1*4] + e1*hw[o1*4+1] + e2*hw[o1*4+2] + e3*hw[o1*4+3];

    float sq = v0*v0 + v1*v1;
    #pragma unroll
    for (int off = 16; off; off >>= 1)
        sq += __shfl_down_sync(0xffffffffu, sq, off);
    if ((t & 31) == 0) rbuf[t >> 5] = sq;
    __syncthreads();
    if (t == 0) {
        float sum = 0.f;
        #pragma unroll
        for (int w = 0; w < 8; ++w) sum += rbuf[w];
        nrm = sum;
    }
    __syncthreads();

    const float scale = 1.f / fmaxf(sqrtf(nrm), 1e-12f);
    out[(size_t)b*512 + o0] = v0*scale;
    out[(size_t)b*512 + o1] = v1*scale;
}

extern "C" void kernel_launch(void* const* d_in, const int* in_sizes, int n_in,
                              void* d_out, int out_size) {
    const float* x     = (const float*)d_in[0];   // (B,16,4,3)
    const float* pos_w = (const float*)d_in[1];   // (16,2)
    const float* l1    = (const float*)d_in[2];   // (20,2)
    const float* l2    = (const float*)d_in[3];   // (16,2)
    const float* hw    = (const float*)d_in[4];   // (512,4)
    const float* hb    = (const float*)d_in[5];   // (512,)
    float* out = (float*)d_out;

    const int B = in_sizes[0] / (16*4*3);
    iqp_embed_kernel<<<B, 256>>>(x, pos_w, l1, l2, hw, hb, out);
}

// round 2
// speedup vs baseline: 1.6048x; 1.6048x over previous
#include <cuda_runtime.h>
#include <math.h>

// QuantumIQPImageEmbedder — closed-form evaluation, slot-parallel version.
//
// rho4 = H4 (Psi Psi^H) H4 where Psi is the phase-multiplied PRODUCT state
// (H16 cancels). G = Psi Psi^H factorizes per qubit: interior traced qubits
// contribute 1, only the two boundary Ising couplings survive.
// The three needed quantum blocks (0,1,3) are computed CONCURRENTLY by
// thread groups of 256 within a 768-thread block.

#define INV_SQRT2F 0.7071067811865476f

__device__ __forceinline__ float2 cmul(float2 a, float2 b) {
    return make_float2(a.x*b.x - a.y*b.y, a.x*b.y + a.y*b.x);
}
__device__ __forceinline__ float2 cmulc(float2 a, float2 b) { // a * conj(b)
    return make_float2(a.x*b.x + a.y*b.y, a.y*b.x - a.x*b.y);
}
__device__ __forceinline__ float2 cadd(float2 a, float2 b) {
    return make_float2(a.x + b.x, a.y + b.y);
}

__global__ void __launch_bounds__(768, 1)
iqp_embed_kernel(const float* __restrict__ x,        // (B,16,4,3)
                 const float* __restrict__ pos_w,    // (16,2)
                 const float* __restrict__ l1,       // (20,2)
                 const float* __restrict__ l2,       // (16,2)
                 const float* __restrict__ hw,       // (512,4)
                 const float* __restrict__ hb,       // (512,)
                 float* __restrict__ out)            // (B,512)
{
    const int b = blockIdx.x;
    const int t = threadIdx.x;          // 768 threads
    const int g = t >> 8;               // slot 0..2 (quantum blocks 0,1,3)
    const int u = t & 255;
    const int i = u >> 4, j = u & 15;

    __shared__ float2 s[3][20][2];
    __shared__ float  l1a[20], l1b[20];
    __shared__ float2 G[3][16][17];
    __shared__ float2 T[3][16][17];
    __shared__ float2 rho4s[3][16][16]; // quantum blocks 0, 1, 3
    __shared__ float2 rho012[64], rho123[64];
    __shared__ float2 rho01[16], rho23[16];
    __shared__ float2 rq0[4], rq3[4];
    __shared__ float2 rk0[64], rk3[64];
    __shared__ float  evals[4];
    __shared__ float  rbuf[8];
    __shared__ float  rbuf2[16];
    __shared__ float  nrm;

    // ---------- Phase 1a: single-qubit states (20 threads per slot) ----------
    if (t < 20) { l1a[t] = l1[2*t]; l1b[t] = l1[2*t + 1]; }

    if (u < 20) {
        const int kb = (g == 2) ? 3 : g;
        const int q  = u;
        const int p  = 4*kb + q/5;
        const int jj = q % 5;
        float2 w0, w1;
        if (jj < 4) {
            const float* xp = x + ((size_t)(b*16 + p)*4 + jj)*3;
            float cx, sx, cy, sy, cz, sz;
            __sincosf(0.5f*xp[0], &sx, &cx);
            __sincosf(0.5f*xp[1], &sy, &cy);
            __sincosf(0.5f*xp[2], &sz, &cz);
            w0 = make_float2(cy*cx,  sy*sx);
            w1 = make_float2(sy*cx, -cy*sx);
            float2 pz = make_float2(cz, -sz);   // e^{-i hz}
            w0 = cmul (w0, pz);
            w1 = cmulc(w1, pz);
        } else {
            float cx, sx, cy, sy;
            __sincosf(0.5f*pos_w[2*p],     &sx, &cx);
            __sincosf(0.5f*pos_w[2*p + 1], &sy, &cy);
            w0 = make_float2(cy*cx,  sy*sx);
            w1 = make_float2(sy*cx, -cy*sx);
        }
        s[g][q][0] = make_float2((w0.x + w1.x)*INV_SQRT2F, (w0.y + w1.y)*INV_SQRT2F);
        s[g][q][1] = make_float2((w0.x - w1.x)*INV_SQRT2F, (w0.y - w1.y)*INV_SQRT2F);
    }
    __syncthreads();

    // ---------- Phase 1b: G[i][j] closed form ----------
    {
        const int i0 = (i>>3)&1, i1 = (i>>2)&1, i2 = (i>>1)&1, i3 = i&1;
        const int j0 = (j>>3)&1, j1 = (j>>2)&1, j2 = (j>>1)&1, j3 = j&1;

        float2 A = cmulc(s[g][0][i0], s[g][0][j0]);
        A = cmul(A, cmulc(s[g][1][i1], s[g][1][j1]));
        A = cmul(A, cmulc(s[g][2][i2], s[g][2][j2]));
        A = cmul(A, cmulc(s[g][3][i3], s[g][3][j3]));

        const float zi0 = 1.f - 2.f*i0, zi1 = 1.f - 2.f*i1;
        const float zi2 = 1.f - 2.f*i2, zi3 = 1.f - 2.f*i3;
        const float zj0 = 1.f - 2.f*j0, zj1 = 1.f - 2.f*j1;
        const float zj2 = 1.f - 2.f*j2, zj3 = 1.f - 2.f*j3;

        float D = l1a[0]*(zi0 - zj0) + l1a[1]*(zi1 - zj1)
                + l1a[2]*(zi2 - zj2) + l1a[3]*(zi3 - zj3)
                + l1b[0]*(zi0*zi1 - zj0*zj1)
                + l1b[1]*(zi1*zi2 - zj1*zj2)
                + l1b[2]*(zi2*zi3 - zj2*zj3);
        float sD, cD;
        __sincosf(0.5f*D, &sD, &cD);
        float2 ph = make_float2(cD, -sD);                 // e^{-iD/2}

        const float p40 = s[g][4][0].x*s[g][4][0].x + s[g][4][0].y*s[g][4][0].y;
        const float p41 = s[g][4][1].x*s[g][4][1].x + s[g][4][1].y*s[g][4][1].y;
        const float pa0 = s[g][19][0].x*s[g][19][0].x + s[g][19][0].y*s[g][19][0].y;
        const float pa1 = s[g][19][1].x*s[g][19][1].x + s[g][19][1].y*s[g][19][1].y;

        float s4, c4, s19, c19;
        __sincosf(0.5f*l1b[3] *(zi3 - zj3), &s4,  &c4);
        __sincosf(0.5f*l1b[19]*(zi0 - zj0), &s19, &c19);
        float2 F4  = make_float2((p40 + p41)*c4,  (p41 - p40)*s4);
        float2 F19 = make_float2((pa0 + pa1)*c19, (pa1 - pa0)*s19);

        G[g][i][j] = cmul(cmul(A, ph), cmul(F4, F19));
    }
    __syncthreads();

    // ---------- Phase 1c: T = H4 G ----------
    {
        float2 acc = make_float2(0.f, 0.f);
        #pragma unroll
        for (int kq = 0; kq < 16; ++kq) {
            float2 gg = G[g][kq][j];
            if (__popc(i & kq) & 1) { acc.x -= gg.x; acc.y -= gg.y; }
            else                    { acc.x += gg.x; acc.y += gg.y; }
        }
        T[g][i][j] = acc;
    }
    __syncthreads();

    // ---------- Phase 1d: rho4 = (1/16) T H4 ----------
    {
        float2 acc = make_float2(0.f, 0.f);
        #pragma unroll
        for (int kq = 0; kq < 16; ++kq) {
            float2 tt = T[g][i][kq];
            if (__popc(kq & j) & 1) { acc.x -= tt.x; acc.y -= tt.y; }
            else                    { acc.x += tt.x; acc.y += tt.y; }
        }
        rho4s[g][i][j] = make_float2(acc.x*0.0625f, acc.y*0.0625f);
    }
    __syncthreads();

    // ---------- Phase 2: partial traces ----------
    if (t < 64) {
        const int ii = t >> 3, jj = t & 7;
        rho012[t] = cadd(rho4s[0][2*ii    ][2*jj    ],
                         rho4s[0][2*ii + 1][2*jj + 1]);               // trace q3
        rho123[t] = cadd(rho4s[0][ii][jj], rho4s[0][8 + ii][8 + jj]); // trace q0
    } else if (t < 80) {
        const int v = t - 64, ii = v >> 2, jj = v & 3;
        float2 a = make_float2(0.f, 0.f), c = make_float2(0.f, 0.f);
        #pragma unroll
        for (int xx = 0; xx < 4; ++xx) {
            a = cadd(a, rho4s[0][4*ii + xx][4*jj + xx]);   // rho01 (block 0)
            c = cadd(c, rho4s[0][4*xx + ii][4*xx + jj]);   // rho23 (block 0)
        }
        rho01[v] = a; rho23[v] = c;
    } else if (t < 84) {
        const int v = t - 80, ii = v >> 1, jj = v & 1;
        float2 a = make_float2(0.f, 0.f), c = make_float2(0.f, 0.f);
        #pragma unroll
        for (int xx = 0; xx < 8; ++xx) {
            a = cadd(a, rho4s[1][8*ii + xx][8*jj + xx]);   // rho_q0 (block 1)
            c = cadd(c, rho4s[2][2*xx + ii][2*xx + jj]);   // rho_q3 (block 3)
        }
        rq0[v] = a; rq3[v] = c;
    }
    __syncthreads();

    if (t < 64) {
        const int ii = t >> 3, jj = t & 7;
        rk0[t] = cmul(rq3 [(ii>>2)*2 + (jj>>2)], rho01[(ii&3)*4 + (jj&3)]);
        rk3[t] = cmul(rho23[(ii>>1)*4 + (jj>>1)], rq0 [(ii&1)*2 + (jj&1)]);
    }
    __syncthreads();

    // ---------- Phase 3: Heisenberg expectation values ----------
    if (t < 256) {
        const int kk = t >> 6;               // which e (0..3)
        const int idx = t & 63;
        const int oi = idx >> 3, oj = idx & 7;

        float c1, s1v, c2, s2v, c3, s3v;
        __sincosf(l2[2*kk],                  &s1v, &c1);   // a2[kk]
        __sincosf(l2[2*((kk - 1) & 15) + 1], &s2v, &c2);   // b2[(kk-1)%16]
        __sincosf(l2[2*kk + 1],              &s3v, &c3);   // b2[kk]

        float2 val = make_float2(0.f, 0.f);
        #pragma unroll
        for (int pp = 0; pp < 2; ++pp) {
            const int p = pp ? (oi ^ 2) : oi;
            const float2 cA = pp ? make_float2(0.f, -s1v) : make_float2(c1, 0.f);
            #pragma unroll
            for (int qq = 0; qq < 2; ++qq) {
                const int q = qq ? (p ^ 6) : p;
                const float2 cB = qq ? make_float2(0.f, -s2v) : make_float2(c2, 0.f);
                float2 cC;
                if (q == oj)            cC = make_float2(c3, 0.f);
                else if (q == (oj ^ 3)) cC = make_float2(0.f, -s3v);
                else continue;
                val = cadd(val, cmul(cmul(cA, cB), cC));
            }
        }
        const float dsign = ((oi >> 1) & 1) ? -1.f : 1.f;
        val.x *= dsign; val.y *= dsign;

        const float2* rho = (kk == 0) ? rk0 : (kk == 1) ? rho012
                          : (kk == 2) ? rho123 : rk3;
        const float2 r = rho[oj*8 + oi];
        float contrib = val.x*r.x - val.y*r.y;   // Re(O[i,j] * rho[j,i])

        #pragma unroll
        for (int off = 16; off; off >>= 1)
            contrib += __shfl_down_sync(0xffffffffu, contrib, off);
        if ((t & 31) == 0) rbuf[t >> 5] = contrib;
    }
    __syncthreads();
    if (t < 4) evals[t] = rbuf[2*t] + rbuf[2*t + 1];
    __syncthreads();

    // ---------- Phase 4: head + L2 normalize (512 threads) ----------
    float v0 = 0.f;
    if (t < 512) {
        const float e0 = evals[0], e1 = evals[1], e2 = evals[2], e3 = evals[3];
        v0 = hb[t] + e0*hw[t*4] + e1*hw[t*4+1] + e2*hw[t*4+2] + e3*hw[t*4+3];
        float sq = v0*v0;
        #pragma unroll
        for (int off = 16; off; off >>= 1)
            sq += __shfl_down_sync(0xffffffffu, sq, off);
        if ((t & 31) == 0) rbuf2[t >> 5] = sq;
    }
    __syncthreads();
    if (t == 0) {
        float sum = 0.f;
        #pragma unroll
        for (int w = 0; w < 16; ++w) sum += rbuf2[w];
        nrm = sum;
    }
    __syncthreads();

    if (t < 512) {
        const float scale = 1.f / fmaxf(sqrtf(nrm), 1e-12f);
        out[(size_t)b*512 + t] = v0*scale;
    }
}

extern "C" void kernel_launch(void* const* d_in, const int* in_sizes, int n_in,
                              void* d_out, int out_size) {
    const float* x     = (const float*)d_in[0];   // (B,16,4,3)
    const float* pos_w = (const float*)d_in[1];   // (16,2)
    const float* l1    = (const float*)d_in[2];   // (20,2)
    const float* l2    = (const float*)d_in[3];   // (16,2)
    const float* hw    = (const float*)d_in[4];   // (512,4)
    const float* hb    = (const float*)d_in[5];   // (512,)
    float* out = (float*)d_out;

    const int B = in_sizes[0] / (16*4*3);
    iqp_embed_kernel<<<B, 768>>>(x, pos_w, l1, l2, hw, hb, out);
}

// round 3
// speedup vs baseline: 1.7169x; 1.0699x over previous
#include <cuda_runtime.h>
#include <math.h>

// QuantumIQPImageEmbedder — closed-form, shuffle-WHT, 256-thread version.
//
// rho4 = (1/16) H4 (Psi Psi^H) H4 ; G = Psi Psi^H factorizes per qubit
// (interior traced qubits contribute 1; only boundary Ising couplings survive).
// All 3 needed quantum blocks (0,1,3) live in registers per thread.
// Both 16-point WHTs are shfl_xor butterflies; only the left one needs one
// smem transpose. 7 block barriers total.

#define INV_SQRT2F 0.7071067811865476f

__device__ __forceinline__ float2 cmul(float2 a, float2 b) {
    return make_float2(a.x*b.x - a.y*b.y, a.x*b.y + a.y*b.x);
}
__device__ __forceinline__ float2 cmulc(float2 a, float2 b) { // a * conj(b)
    return make_float2(a.x*b.x + a.y*b.y, a.y*b.x - a.x*b.y);
}
__device__ __forceinline__ float2 cadd(float2 a, float2 b) {
    return make_float2(a.x + b.x, a.y + b.y);
}

__global__ void __launch_bounds__(256, 1)
iqp_embed_kernel(const float* __restrict__ x,        // (B,16,4,3)
                 const float* __restrict__ pos_w,    // (16,2)
                 const float* __restrict__ l1,       // (20,2)
                 const float* __restrict__ l2,       // (16,2)
                 const float* __restrict__ hw,       // (512,4)
                 const float* __restrict__ hb,       // (512,)
                 float* __restrict__ out)            // (B,512)
{
    const int b = blockIdx.x;
    const int t = threadIdx.x;          // 256 threads
    const int i = t >> 4, j = t & 15;

    __shared__ float2 s[3][20][2];
    __shared__ float  l1a[20], l1b[20];
    __shared__ float2 T[3][16][17];
    __shared__ float2 rho4s[3][16][17];
    __shared__ float2 rho012[64], rho123[64];
    __shared__ float2 rho01[16], rho23[16];
    __shared__ float2 rq0[4], rq3[4];
    __shared__ float2 rk0[64], rk3[64];
    __shared__ float  evals[4];
    __shared__ float  rbuf2[8];

    // ---------- Prefetch everything independent (hidden behind phase 1) ----
    const float4 w0v = ((const float4*)hw)[t];
    const float4 w1v = ((const float4*)hw)[t + 256];
    const float  hb0 = hb[t], hb1 = hb[t + 256];

    float c1, s1v, c2, s2v, c3, s3v;     // phase-3 trig, warps 0-3 (kk = warp)
    if (t < 128) {
        const int kk = t >> 5;
        __sincosf(l2[2*kk],                  &s1v, &c1);
        __sincosf(l2[2*((kk - 1) & 15) + 1], &s2v, &c2);
        __sincosf(l2[2*kk + 1],              &s3v, &c3);
    }

    if (t < 20) { l1a[t] = l1[2*t]; l1b[t] = l1[2*t + 1]; }

    // ---------- Phase 1a: single-qubit states, all 3 slots (60 threads) ----
    if (t < 60) {
        const int g  = t / 20;
        const int q  = t % 20;
        const int kb = (g == 2) ? 3 : g;
        const int p  = 4*kb + q/5;
        const int jj = q % 5;
        float2 w0, w1;
        if (jj < 4) {
            const float* xp = x + ((size_t)(b*16 + p)*4 + jj)*3;
            float cx, sx, cy, sy, cz, sz;
            __sincosf(0.5f*xp[0], &sx, &cx);
            __sincosf(0.5f*xp[1], &sy, &cy);
            __sincosf(0.5f*xp[2], &sz, &cz);
            w0 = make_float2(cy*cx,  sy*sx);
            w1 = make_float2(sy*cx, -cy*sx);
            float2 pz = make_float2(cz, -sz);   // e^{-i hz}
            w0 = cmul (w0, pz);
            w1 = cmulc(w1, pz);
        } else {
            float cx, sx, cy, sy;
            __sincosf(0.5f*pos_w[2*p],     &sx, &cx);
            __sincosf(0.5f*pos_w[2*p + 1], &sy, &cy);
            w0 = make_float2(cy*cx,  sy*sx);
            w1 = make_float2(sy*cx, -cy*sx);
        }
        s[g][q][0] = make_float2((w0.x + w1.x)*INV_SQRT2F, (w0.y + w1.y)*INV_SQRT2F);
        s[g][q][1] = make_float2((w0.x - w1.x)*INV_SQRT2F, (w0.y - w1.y)*INV_SQRT2F);
    }
    __syncthreads();                                            // B1

    // ---------- Phase 1b: G (3 slots in regs) + right WHT via shuffles -----
    float2 Gv[3];
    {
        const int i0 = (i>>3)&1, i1 = (i>>2)&1, i2 = (i>>1)&1, i3 = i&1;
        const int j0 = (j>>3)&1, j1 = (j>>2)&1, j2 = (j>>1)&1, j3 = j&1;

        const float zi0 = 1.f - 2.f*i0, zi1 = 1.f - 2.f*i1;
        const float zi2 = 1.f - 2.f*i2, zi3 = 1.f - 2.f*i3;
        const float zj0 = 1.f - 2.f*j0, zj1 = 1.f - 2.f*j1;
        const float zj2 = 1.f - 2.f*j2, zj3 = 1.f - 2.f*j3;

        // slot-independent phase terms
        float D = l1a[0]*(zi0 - zj0) + l1a[1]*(zi1 - zj1)
                + l1a[2]*(zi2 - zj2) + l1a[3]*(zi3 - zj3)
                + l1b[0]*(zi0*zi1 - zj0*zj1)
                + l1b[1]*(zi1*zi2 - zj1*zj2)
                + l1b[2]*(zi2*zi3 - zj2*zj3);
        float sD, cD;  __sincosf(0.5f*D, &sD, &cD);
        const float2 ph = make_float2(cD, -sD);                  // e^{-iD/2}
        float s4, c4, s19, c19;
        __sincosf(0.5f*l1b[3] *(zi3 - zj3), &s4,  &c4);
        __sincosf(0.5f*l1b[19]*(zi0 - zj0), &s19, &c19);

        #pragma unroll
        for (int g = 0; g < 3; ++g) {
            float2 A = cmulc(s[g][0][i0], s[g][0][j0]);
            A = cmul(A, cmulc(s[g][1][i1], s[g][1][j1]));
            A = cmul(A, cmulc(s[g][2][i2], s[g][2][j2]));
            A = cmul(A, cmulc(s[g][3][i3], s[g][3][j3]));

            const float p40 = s[g][4][0].x*s[g][4][0].x + s[g][4][0].y*s[g][4][0].y;
            const float p41 = s[g][4][1].x*s[g][4][1].x + s[g][4][1].y*s[g][4][1].y;
            const float pa0 = s[g][19][0].x*s[g][19][0].x + s[g][19][0].y*s[g][19][0].y;
            const float pa1 = s[g][19][1].x*s[g][19][1].x + s[g][19][1].y*s[g][19][1].y;

            const float2 F4  = make_float2((p40 + p41)*c4,  (p41 - p40)*s4);
            const float2 F19 = make_float2((pa0 + pa1)*c19, (pa1 - pa0)*s19);
            Gv[g] = cmul(cmul(A, ph), cmul(F4, F19));
        }
    }
    // right WHT over j (low 4 lane bits): T = G H4
    #pragma unroll
    for (int m = 1; m < 16; m <<= 1) {
        #pragma unroll
        for (int g = 0; g < 3; ++g) {
            const float px = __shfl_xor_sync(0xffffffffu, Gv[g].x, m);
            const float py = __shfl_xor_sync(0xffffffffu, Gv[g].y, m);
            if (j & m) { Gv[g].x = px - Gv[g].x; Gv[g].y = py - Gv[g].y; }
            else       { Gv[g].x += px;         Gv[g].y += py;         }
        }
    }
    #pragma unroll
    for (int g = 0; g < 3; ++g) T[g][i][j] = Gv[g];
    __syncthreads();                                            // B2

    // ---------- Phase 1c: left WHT (transposed remap) → rho4 ---------------
    {
        const int ti = t & 15, tj = t >> 4;
        float2 R[3];
        #pragma unroll
        for (int g = 0; g < 3; ++g) R[g] = T[g][ti][tj];
        #pragma unroll
        for (int m = 1; m < 16; m <<= 1) {
            #pragma unroll
            for (int g = 0; g < 3; ++g) {
                const float px = __shfl_xor_sync(0xffffffffu, R[g].x, m);
                const float py = __shfl_xor_sync(0xffffffffu, R[g].y, m);
                if (ti & m) { R[g].x = px - R[g].x; R[g].y = py - R[g].y; }
                else        { R[g].x += px;         R[g].y += py;         }
            }
        }
        #pragma unroll
        for (int g = 0; g < 3; ++g)
            rho4s[g][ti][tj] = make_float2(R[g].x*0.0625f, R[g].y*0.0625f);
    }
    __syncthreads();                                            // B3

    // ---------- Phase 2: partial traces ----------
    if (t < 64) {
        const int ii = t >> 3, jj = t & 7;
        rho012[t] = cadd(rho4s[0][2*ii    ][2*jj    ],
                         rho4s[0][2*ii + 1][2*jj + 1]);               // trace q3
        rho123[t] = cadd(rho4s[0][ii][jj], rho4s[0][8 + ii][8 + jj]); // trace q0
    } else if (t < 80) {
        const int v = t - 64, ii = v >> 2, jj = v & 3;
        float2 a = make_float2(0.f, 0.f), c = make_float2(0.f, 0.f);
        #pragma unroll
        for (int xx = 0; xx < 4; ++xx) {
            a = cadd(a, rho4s[0][4*ii + xx][4*jj + xx]);   // rho01 (block 0)
            c = cadd(c, rho4s[0][4*xx + ii][4*xx + jj]);   // rho23 (block 0)
        }
        rho01[v] = a; rho23[v] = c;
    } else if (t < 84) {
        const int v = t - 80, ii = v >> 1, jj = v & 1;
        float2 a = make_float2(0.f, 0.f), c = make_float2(0.f, 0.f);
        #pragma unroll
        for (int xx = 0; xx < 8; ++xx) {
            a = cadd(a, rho4s[1][8*ii + xx][8*jj + xx]);   // rho_q0 (block 1)
            c = cadd(c, rho4s[2][2*xx + ii][2*xx + jj]);   // rho_q3 (block 3)
        }
        rq0[v] = a; rq3[v] = c;
    }
    __syncthreads();                                            // B4

    if (t < 64) {
        const int ii = t >> 3, jj = t & 7;
        rk0[t] = cmul(rq3 [(ii>>2)*2 + (jj>>2)], rho01[(ii&3)*4 + (jj&3)]);
        rk3[t] = cmul(rho23[(ii>>1)*4 + (jj>>1)], rq0 [(ii&1)*2 + (jj&1)]);
    }
    __syncthreads();                                            // B5

    // ---------- Phase 3: Heisenberg expectation values (warps 0-3) --------
    if (t < 128) {
        const int kk   = t >> 5;
        const int lane = t & 31;
        const float2* rho = (kk == 0) ? rk0 : (kk == 1) ? rho012
                          : (kk == 2) ? rho123 : rk3;
        float contrib = 0.f;
        #pragma unroll
        for (int e = 0; e < 2; ++e) {
            const int idx = 2*lane + e;
            const int oi = idx >> 3, oj = idx & 7;
            float2 val = make_float2(0.f, 0.f);
            #pragma unroll
            for (int pp = 0; pp < 2; ++pp) {
                const int p = pp ? (oi ^ 2) : oi;
                const float2 cA = pp ? make_float2(0.f, -s1v) : make_float2(c1, 0.f);
                #pragma unroll
                for (int qq = 0; qq < 2; ++qq) {
                    const int q = qq ? (p ^ 6) : p;
                    const float2 cB = qq ? make_float2(0.f, -s2v) : make_float2(c2, 0.f);
                    float2 cC;
                    if (q == oj)            cC = make_float2(c3, 0.f);
                    else if (q == (oj ^ 3)) cC = make_float2(0.f, -s3v);
                    else continue;
                    val = cadd(val, cmul(cmul(cA, cB), cC));
                }
            }
            const float dsign = ((oi >> 1) & 1) ? -1.f : 1.f;
            const float2 r = rho[oj*8 + oi];
            contrib += dsign*(val.x*r.x - val.y*r.y);   // Re(O[i,j]*rho[j,i])
        }
        #pragma unroll
        for (int off = 16; off; off >>= 1)
            contrib += __shfl_down_sync(0xffffffffu, contrib, off);
        if (lane == 0) evals[kk] = contrib;
    }
    __syncthreads();                                            // B6

    // ---------- Phase 4: head + L2 normalize (preloaded weights) ----------
    const float e0 = evals[0], e1 = evals[1], e2 = evals[2], e3 = evals[3];
    const float v0 = hb0 + e0*w0v.x + e1*w0v.y + e2*w0v.z + e3*w0v.w;
    const float v1 = hb1 + e0*w1v.x + e1*w1v.y + e2*w1v.z + e3*w1v.w;

    float sq = v0*v0 + v1*v1;
    #pragma unroll
    for (int off = 16; off; off >>= 1)
        sq += __shfl_down_sync(0xffffffffu, sq, off);
    if ((t & 31) == 0) rbuf2[t >> 5] = sq;
    __syncthreads();                                            // B7

    float nrm = 0.f;
    #pragma unroll
    for (int w = 0; w < 8; ++w) nrm += rbuf2[w];
    const float scale = 1.f / fmaxf(sqrtf(nrm), 1e-12f);
    out[(size_t)b*512 + t      ] = v0*scale;
    out[(size_t)b*512 + t + 256] = v1*scale;
}

extern "C" void kernel_launch(void* const* d_in, const int* in_sizes, int n_in,
                              void* d_out, int out_size) {
    const float* x     = (const float*)d_in[0];   // (B,16,4,3)
    const float* pos_w = (const float*)d_in[1];   // (16,2)
    const float* l1    = (const float*)d_in[2];   // (20,2)
    const float* l2    = (const float*)d_in[3];   // (16,2)
    const float* hw    = (const float*)d_in[4];   // (512,4)
    const float* hb    = (const float*)d_in[5];   // (512,)
    float* out = (float*)d_out;

    const int B = in_sizes[0] / (16*4*3);
    iqp_embed_kernel<<<B, 256>>>(x, pos_w, l1, l2, hw, hb, out);
}